// round 1
// baseline (speedup 1.0000x reference)
#include <cuda_runtime.h>

// Problem constants (fixed by reference)
#define B   8192   // batch
#define D   256    // input dim
#define C   512    // num centers
#define NORD 9     // order+1
#define F   256    // output dim

// ---------------- scratch (static device globals; no allocation) ----------
__device__ float g_dist[(size_t)B * C];   // 16 MB distance matrix
__device__ float g_x2[B];
__device__ float g_c2[C];
__device__ unsigned int g_minmax[2];      // [0]=min bits, [1]=max bits (dist>=0)

// ---------------- kernel 0: reset min/max ---------------------------------
__global__ void k_init() {
    g_minmax[0] = 0x7f800000u;  // +inf
    g_minmax[1] = 0u;           // 0.0f
}

// ---------------- kernel 1: row squared norms (one warp per row) ----------
__global__ void __launch_bounds__(256) k_sq(const float* __restrict__ x,
                                            const float* __restrict__ cen) {
    int warp = (blockIdx.x * blockDim.x + threadIdx.x) >> 5;
    int lane = threadIdx.x & 31;
    if (warp >= B + C) return;
    const float* src;
    float* dst;
    if (warp < B) { src = x   + (size_t)warp * D;       dst = &g_x2[warp]; }
    else          { src = cen + (size_t)(warp - B) * D; dst = &g_c2[warp - B]; }
    float s = 0.f;
    const float4* p = (const float4*)src;
    #pragma unroll
    for (int i = lane; i < D / 4; i += 32) {
        float4 v = p[i];
        s += v.x * v.x + v.y * v.y + v.z * v.z + v.w * v.w;
    }
    #pragma unroll
    for (int o = 16; o > 0; o >>= 1) s += __shfl_xor_sync(0xffffffffu, s, o);
    if (lane == 0) *dst = s;
}

// ---------------- kernel 2: distance GEMM + global min/max ----------------
// dist[m,n] = sqrt(max(x2[m] + c2[n] - 2*dot(x[m],cen[n]), 0))
#define BM 64
#define BN 64
#define BK 16

__global__ void __launch_bounds__(256) k_dist(const float* __restrict__ x,
                                              const float* __restrict__ cen) {
    __shared__ __align__(16) float As[BK][BM + 4];
    __shared__ __align__(16) float Bs[BK][BN + 4];
    __shared__ unsigned int s_min, s_max;

    int tid = threadIdx.x;
    int m0 = blockIdx.y * BM;
    int n0 = blockIdx.x * BN;
    int tm = tid >> 4;        // 0..15
    int tn = tid & 15;        // 0..15
    int lr = tid >> 2;        // loader row 0..63
    int lk = (tid & 3) * 4;   // loader k offset 0/4/8/12

    if (tid == 0) { s_min = 0x7f800000u; s_max = 0u; }

    float acc[4][4] = {};

    for (int k0 = 0; k0 < D; k0 += BK) {
        float4 av = *(const float4*)(x   + (size_t)(m0 + lr) * D + k0 + lk);
        float4 bv = *(const float4*)(cen + (size_t)(n0 + lr) * D + k0 + lk);
        As[lk + 0][lr] = av.x; As[lk + 1][lr] = av.y;
        As[lk + 2][lr] = av.z; As[lk + 3][lr] = av.w;
        Bs[lk + 0][lr] = bv.x; Bs[lk + 1][lr] = bv.y;
        Bs[lk + 2][lr] = bv.z; Bs[lk + 3][lr] = bv.w;
        __syncthreads();
        #pragma unroll
        for (int k = 0; k < BK; k++) {
            float4 a4 = *(const float4*)&As[k][tm * 4];
            float4 b4 = *(const float4*)&Bs[k][tn * 4];
            float a[4] = {a4.x, a4.y, a4.z, a4.w};
            float b[4] = {b4.x, b4.y, b4.z, b4.w};
            #pragma unroll
            for (int i = 0; i < 4; i++)
                #pragma unroll
                for (int j = 0; j < 4; j++)
                    acc[i][j] = fmaf(a[i], b[j], acc[i][j]);
        }
        __syncthreads();
    }

    float xs[4], cs[4];
    #pragma unroll
    for (int i = 0; i < 4; i++) xs[i] = g_x2[m0 + tm * 4 + i];
    #pragma unroll
    for (int j = 0; j < 4; j++) cs[j] = g_c2[n0 + tn * 4 + j];

    float lmin = 3.4e38f, lmax = 0.f;
    #pragma unroll
    for (int i = 0; i < 4; i++) {
        float4 st;
        float d[4];
        #pragma unroll
        for (int j = 0; j < 4; j++) {
            float d2 = xs[i] + cs[j] - 2.0f * acc[i][j];
            d[j] = sqrtf(fmaxf(d2, 0.0f));
            lmin = fminf(lmin, d[j]);
            lmax = fmaxf(lmax, d[j]);
        }
        st.x = d[0]; st.y = d[1]; st.z = d[2]; st.w = d[3];
        *(float4*)&g_dist[(size_t)(m0 + tm * 4 + i) * C + n0 + tn * 4] = st;
    }

    #pragma unroll
    for (int o = 16; o > 0; o >>= 1) {
        lmin = fminf(lmin, __shfl_xor_sync(0xffffffffu, lmin, o));
        lmax = fmaxf(lmax, __shfl_xor_sync(0xffffffffu, lmax, o));
    }
    if ((tid & 31) == 0) {
        atomicMin(&s_min, __float_as_uint(lmin));
        atomicMax(&s_max, __float_as_uint(lmax));
    }
    __syncthreads();
    if (tid == 0) {
        atomicMin(&g_minmax[0], s_min);
        atomicMax(&g_minmax[1], s_max);
    }
}

// ---------------- kernel 3: basis + output GEMM ----------------------------
// out[b,f] = sum_c sum_n P_n(t[b,c]) * W[c,n,f]
// GEMM: M=B, N=F, K=C*NORD. A (basis) produced on the fly into shared.
#define OBM 64
#define OBN 64
#define OCC 4                 // centers per K-chunk
#define OCK (OCC * NORD)      // 36

__global__ void __launch_bounds__(256) k_out(const float* __restrict__ w,
                                             float* __restrict__ out) {
    __shared__ __align__(16) float As[OCK][OBM + 4];  // basis [k=(cc*9+n)][m]
    __shared__ __align__(16) float Bs[OCK][OBN + 4];  // weights [k][f]

    int tid = threadIdx.x;
    int m0 = blockIdx.y * OBM;
    int f0 = blockIdx.x * OBN;
    int tm = tid >> 4;
    int tn = tid & 15;
    int bm = tid & 63;   // basis producer: row within tile
    int bc = tid >> 6;   // basis producer: center within chunk (0..3)

    float dmin = __uint_as_float(g_minmax[0]);
    float dmax = __uint_as_float(g_minmax[1]);
    float scale = 2.0f / (dmax - dmin);

    float acc[4][4] = {};

    for (int c0 = 0; c0 < C; c0 += OCC) {
        // --- produce Legendre basis for (bm, c0+bc) ---
        float t = (g_dist[(size_t)(m0 + bm) * C + c0 + bc] - dmin) * scale - 1.0f;
        float p0 = 1.0f, p1 = t;
        As[bc * NORD + 0][bm] = p0;
        As[bc * NORD + 1][bm] = p1;
        #pragma unroll
        for (int n = 1; n < NORD - 1; n++) {
            float p2 = ((2.0f * n + 1.0f) * t * p1 - (float)n * p0) * (1.0f / (n + 1.0f));
            As[bc * NORD + n + 1][bm] = p2;
            p0 = p1; p1 = p2;
        }
        // --- stage W chunk: OCK x OBN ---
        #pragma unroll
        for (int i = 0; i < 9; i++) {
            int idx = i * 256 + tid;          // 0..2303
            int kk  = idx >> 6;               // 0..35
            int col = idx & 63;
            int c = c0 + kk / NORD;
            int n = kk - (kk / NORD) * NORD;
            Bs[kk][col] = w[((size_t)c * NORD + n) * F + f0 + col];
        }
        __syncthreads();
        #pragma unroll
        for (int k = 0; k < OCK; k++) {
            float4 a4 = *(const float4*)&As[k][tm * 4];
            float4 b4 = *(const float4*)&Bs[k][tn * 4];
            float a[4] = {a4.x, a4.y, a4.z, a4.w};
            float b[4] = {b4.x, b4.y, b4.z, b4.w};
            #pragma unroll
            for (int i = 0; i < 4; i++)
                #pragma unroll
                for (int j = 0; j < 4; j++)
                    acc[i][j] = fmaf(a[i], b[j], acc[i][j]);
        }
        __syncthreads();
    }

    #pragma unroll
    for (int i = 0; i < 4; i++) {
        float4 st = {acc[i][0], acc[i][1], acc[i][2], acc[i][3]};
        *(float4*)&out[(size_t)(m0 + tm * 4 + i) * F + f0 + tn * 4] = st;
    }
}

// ---------------- launch ---------------------------------------------------
extern "C" void kernel_launch(void* const* d_in, const int* in_sizes, int n_in,
                              void* d_out, int out_size) {
    const float* x   = (const float*)d_in[0];   // [8192,256]
    const float* cen = (const float*)d_in[1];   // [512,256]
    const float* w   = (const float*)d_in[2];   // [512,9,256]
    float* out = (float*)d_out;                 // [8192,256]

    k_init<<<1, 1>>>();
    int sq_warps = B + C;                       // 8704 warps, 8 per block
    k_sq<<<(sq_warps + 7) / 8, 256>>>(x, cen);
    k_dist<<<dim3(C / BN, B / BM), 256>>>(x, cen);
    k_out<<<dim3(F / OBN, B / OBM), 256>>>(w, out);
}

// round 3
// speedup vs baseline: 2.0290x; 2.0290x over previous
#include <cuda_runtime.h>
#include <cuda_bf16.h>
#include <cstdint>

// Problem constants (fixed by reference)
#define B_   8192   // batch
#define D_   256    // input dim
#define C_   512    // num centers
#define NORD 9      // order+1
#define F_   256    // output dim
#define KTOT (C_ * NORD)   // 4608

// ---------------- scratch (static device globals; no allocation) ----------
__device__ __align__(16) float g_dist[(size_t)B_ * C_];   // 16 MB
__device__ float g_x2[B_];
__device__ float g_c2[C_];
__device__ unsigned int g_minmax[2];
// W split to bf16 hi/lo, layout [f][cb][n][ci]: index f*4608 + cb*144 + n*16 + ci,
// where c = cb*16 + ci.
__device__ __align__(16) __nv_bfloat16 g_wt_hi[(size_t)F_ * KTOT];
__device__ __align__(16) __nv_bfloat16 g_wt_lo[(size_t)F_ * KTOT];

// ==================== small helpers ========================================
__device__ __forceinline__ uint32_t smem_u32(const void* p) {
    uint32_t a;
    asm("{ .reg .u64 t; cvta.to.shared.u64 t, %1; cvt.u32.u64 %0, t; }"
        : "=r"(a) : "l"(p));
    return a;
}

__device__ __forceinline__ void ldsm4(uint32_t* r, uint32_t addr) {
    asm volatile("ldmatrix.sync.aligned.m8n8.x4.shared.b16 {%0,%1,%2,%3}, [%4];"
        : "=r"(r[0]), "=r"(r[1]), "=r"(r[2]), "=r"(r[3]) : "r"(addr));
}

__device__ __forceinline__ void mma_bf16(float* d, const uint32_t* a,
                                         uint32_t b0, uint32_t b1) {
    asm volatile(
        "mma.sync.aligned.m16n8k16.row.col.f32.bf16.bf16.f32 "
        "{%0,%1,%2,%3}, {%4,%5,%6,%7}, {%8,%9}, {%0,%1,%2,%3};"
        : "+f"(d[0]), "+f"(d[1]), "+f"(d[2]), "+f"(d[3])
        : "r"(a[0]), "r"(a[1]), "r"(a[2]), "r"(a[3]), "r"(b0), "r"(b1));
}

// ---------------- kernel 0: reset min/max ---------------------------------
__global__ void k_init() {
    g_minmax[0] = 0x7f800000u;
    g_minmax[1] = 0u;
}

// ---------------- kernel 1: row squared norms ------------------------------
__global__ void __launch_bounds__(256) k_sq(const float* __restrict__ x,
                                            const float* __restrict__ cen) {
    int warp = (blockIdx.x * blockDim.x + threadIdx.x) >> 5;
    int lane = threadIdx.x & 31;
    if (warp >= B_ + C_) return;
    const float* src;
    float* dst;
    if (warp < B_) { src = x   + (size_t)warp * D_;        dst = &g_x2[warp]; }
    else           { src = cen + (size_t)(warp - B_) * D_; dst = &g_c2[warp - B_]; }
    float s = 0.f;
    const float4* p = (const float4*)src;
    #pragma unroll
    for (int i = lane; i < D_ / 4; i += 32) {
        float4 v = p[i];
        s += v.x * v.x + v.y * v.y + v.z * v.z + v.w * v.w;
    }
    #pragma unroll
    for (int o = 16; o > 0; o >>= 1) s += __shfl_xor_sync(0xffffffffu, s, o);
    if (lane == 0) *dst = s;
}

// ---------------- kernel 2: distance GEMM + global min/max ----------------
#define BM 64
#define BN 64
#define BK 16

__global__ void __launch_bounds__(256) k_dist(const float* __restrict__ x,
                                              const float* __restrict__ cen) {
    __shared__ __align__(16) float As[BK][BM + 4];
    __shared__ __align__(16) float Bs[BK][BN + 4];
    __shared__ unsigned int s_min, s_max;

    int tid = threadIdx.x;
    int m0 = blockIdx.y * BM;
    int n0 = blockIdx.x * BN;
    int tm = tid >> 4;
    int tn = tid & 15;
    int lr = tid >> 2;
    int lk = (tid & 3) * 4;

    if (tid == 0) { s_min = 0x7f800000u; s_max = 0u; }

    float acc[4][4] = {};

    for (int k0 = 0; k0 < D_; k0 += BK) {
        float4 av = *(const float4*)(x   + (size_t)(m0 + lr) * D_ + k0 + lk);
        float4 bv = *(const float4*)(cen + (size_t)(n0 + lr) * D_ + k0 + lk);
        As[lk + 0][lr] = av.x; As[lk + 1][lr] = av.y;
        As[lk + 2][lr] = av.z; As[lk + 3][lr] = av.w;
        Bs[lk + 0][lr] = bv.x; Bs[lk + 1][lr] = bv.y;
        Bs[lk + 2][lr] = bv.z; Bs[lk + 3][lr] = bv.w;
        __syncthreads();
        #pragma unroll
        for (int k = 0; k < BK; k++) {
            float4 a4 = *(const float4*)&As[k][tm * 4];
            float4 b4 = *(const float4*)&Bs[k][tn * 4];
            float a[4] = {a4.x, a4.y, a4.z, a4.w};
            float b[4] = {b4.x, b4.y, b4.z, b4.w};
            #pragma unroll
            for (int i = 0; i < 4; i++)
                #pragma unroll
                for (int j = 0; j < 4; j++)
                    acc[i][j] = fmaf(a[i], b[j], acc[i][j]);
        }
        __syncthreads();
    }

    float xs[4], cs[4];
    #pragma unroll
    for (int i = 0; i < 4; i++) xs[i] = g_x2[m0 + tm * 4 + i];
    #pragma unroll
    for (int j = 0; j < 4; j++) cs[j] = g_c2[n0 + tn * 4 + j];

    float lmin = 3.4e38f, lmax = 0.f;
    #pragma unroll
    for (int i = 0; i < 4; i++) {
        float4 st;
        float d[4];
        #pragma unroll
        for (int j = 0; j < 4; j++) {
            float d2 = xs[i] + cs[j] - 2.0f * acc[i][j];
            d[j] = sqrtf(fmaxf(d2, 0.0f));
            lmin = fminf(lmin, d[j]);
            lmax = fmaxf(lmax, d[j]);
        }
        st.x = d[0]; st.y = d[1]; st.z = d[2]; st.w = d[3];
        *(float4*)&g_dist[(size_t)(m0 + tm * 4 + i) * C_ + n0 + tn * 4] = st;
    }

    #pragma unroll
    for (int o = 16; o > 0; o >>= 1) {
        lmin = fminf(lmin, __shfl_xor_sync(0xffffffffu, lmin, o));
        lmax = fmaxf(lmax, __shfl_xor_sync(0xffffffffu, lmax, o));
    }
    if ((tid & 31) == 0) {
        atomicMin(&s_min, __float_as_uint(lmin));
        atomicMax(&s_max, __float_as_uint(lmax));
    }
    __syncthreads();
    if (tid == 0) {
        atomicMin(&g_minmax[0], s_min);
        atomicMax(&g_minmax[1], s_max);
    }
}

// ---------------- kernel 3: split W into bf16 hi/lo, layout [f][cb][n][ci] -
__global__ void __launch_bounds__(256) k_prep(const float* __restrict__ w) {
    int cb = blockIdx.x;           // 0..31 (center blocks of 16)
    int f  = threadIdx.x;          // 0..255
    __nv_bfloat16* oh = g_wt_hi + (size_t)f * KTOT + cb * 144;
    __nv_bfloat16* ol = g_wt_lo + (size_t)f * KTOT + cb * 144;
    #pragma unroll
    for (int n = 0; n < NORD; n++) {
        #pragma unroll
        for (int ci = 0; ci < 16; ci += 2) {
            float v0 = w[((size_t)(cb * 16 + ci)     * NORD + n) * F_ + f];
            float v1 = w[((size_t)(cb * 16 + ci + 1) * NORD + n) * F_ + f];
            __nv_bfloat162 h = __floats2bfloat162_rn(v0, v1);
            float h0 = __bfloat162float(h.x), h1 = __bfloat162float(h.y);
            __nv_bfloat162 l = __floats2bfloat162_rn(v0 - h0, v1 - h1);
            *(__nv_bfloat162*)(oh + n * 16 + ci) = h;
            *(__nv_bfloat162*)(ol + n * 16 + ci) = l;
        }
    }
}

// ---------------- kernel 4: bf16x3 mma.sync output GEMM --------------------
// out[m,f] = sum_k basis[m,k] * Wt[f,k];  K chunked as 32 blocks of 144
// (16 centers x 9 orders, k = n*16 + ci). CTA tile 128x128, 8 warps 32x64.
#define AROWB 304                       // padded row stride in bytes (144*2 + 16)
#define OFF_AH 0
#define OFF_AL (OFF_AH + 128 * AROWB)   // 38912
#define OFF_BH (OFF_AL + 128 * AROWB)   // 77824
#define OFF_BL (OFF_BH + 128 * AROWB)   // 116736
#define SMEM_TOTAL (OFF_BL + 128 * AROWB)  // 155648

__global__ void __launch_bounds__(256, 1) k_out_mma(float* __restrict__ out) {
    extern __shared__ char smem[];
    const uint32_t sb = smem_u32(smem);

    const int tid  = threadIdx.x;
    const int wid  = tid >> 5;
    const int lane = tid & 31;
    const int wm   = wid & 3;     // warp m position (4)
    const int wn   = wid >> 2;    // warp n position (2)
    const int m0   = blockIdx.y * 128;
    const int f0   = blockIdx.x * 128;

    const float dmin  = __uint_as_float(g_minmax[0]);
    const float dmax  = __uint_as_float(g_minmax[1]);
    const float scale = 2.0f / (dmax - dmin);

    // ---- producer mapping: row + 8 centers of the 16 ----
    const int prow  = tid & 127;
    const int phalf = tid >> 7;                 // 0/1 -> centers 0-7 / 8-15
    char* aStH = smem + OFF_AH + prow * AROWB + phalf * 16;
    char* aStL = smem + OFF_AL + prow * AROWB + phalf * 16;
    const float* dbase = g_dist + (size_t)(m0 + prow) * C_ + phalf * 8;

    // ---- B stage mapping: f row + half of the 144 k's ----
    const int bf    = tid >> 1;
    const int bhalf = tid & 1;
    const __nv_bfloat16* wsrcH = g_wt_hi + (size_t)(f0 + bf) * KTOT + bhalf * 72;
    const __nv_bfloat16* wsrcL = g_wt_lo + (size_t)(f0 + bf) * KTOT + bhalf * 72;
    char* bStH = smem + OFF_BH + bf * AROWB + bhalf * 144;
    char* bStL = smem + OFF_BL + bf * AROWB + bhalf * 144;

    // ---- ldmatrix per-lane base offsets ----
    const uint32_t lrow  = lane & 15;
    const uint32_t kside = (lane >> 4) * 16;    // byte offset for k-half
    const uint32_t aoff  = (wm * 32 + lrow) * AROWB + kside;
    const uint32_t boff  = (wn * 64 + lrow) * AROWB + kside;

    float acc[2][8][4];
    #pragma unroll
    for (int mt = 0; mt < 2; mt++)
        #pragma unroll
        for (int j = 0; j < 8; j++)
            #pragma unroll
            for (int e = 0; e < 4; e++) acc[mt][j][e] = 0.0f;

    for (int cb = 0; cb < 32; cb++) {
        // ================= produce basis chunk (hi/lo bf16) =================
        {
            float4 dv0 = *(const float4*)(dbase + cb * 16);
            float4 dv1 = *(const float4*)(dbase + cb * 16 + 4);
            float t[8], pa[8], pb[8];
            t[0] = fmaf(dv0.x - dmin, scale, -1.0f);
            t[1] = fmaf(dv0.y - dmin, scale, -1.0f);
            t[2] = fmaf(dv0.z - dmin, scale, -1.0f);
            t[3] = fmaf(dv0.w - dmin, scale, -1.0f);
            t[4] = fmaf(dv1.x - dmin, scale, -1.0f);
            t[5] = fmaf(dv1.y - dmin, scale, -1.0f);
            t[6] = fmaf(dv1.z - dmin, scale, -1.0f);
            t[7] = fmaf(dv1.w - dmin, scale, -1.0f);

            // n = 0: P_0 = 1 exactly
            uint4 ones = make_uint4(0x3F803F80u, 0x3F803F80u, 0x3F803F80u, 0x3F803F80u);
            uint4 zero = make_uint4(0u, 0u, 0u, 0u);
            *(uint4*)(aStH) = ones;
            *(uint4*)(aStL) = zero;
            #pragma unroll
            for (int jj = 0; jj < 8; jj++) { pa[jj] = 1.0f; pb[jj] = t[jj]; }

            #pragma unroll
            for (int n = 1; n < NORD; n++) {
                if (n >= 2) {
                    const float an = (2.0f * n - 1.0f) / (float)n;
                    const float bn = (float)(n - 1) / (float)n;
                    #pragma unroll
                    for (int jj = 0; jj < 8; jj++) {
                        float p2 = an * t[jj] * pb[jj] - bn * pa[jj];
                        pa[jj] = pb[jj];
                        pb[jj] = p2;
                    }
                }
                uint32_t hw[4], lw[4];
                #pragma unroll
                for (int q = 0; q < 4; q++) {
                    float v0 = pb[q * 2], v1 = pb[q * 2 + 1];
                    __nv_bfloat162 h = __floats2bfloat162_rn(v0, v1);
                    float h0 = __bfloat162float(h.x), h1 = __bfloat162float(h.y);
                    __nv_bfloat162 l = __floats2bfloat162_rn(v0 - h0, v1 - h1);
                    hw[q] = *(uint32_t*)&h;
                    lw[q] = *(uint32_t*)&l;
                }
                *(uint4*)(aStH + n * 32) = make_uint4(hw[0], hw[1], hw[2], hw[3]);
                *(uint4*)(aStL + n * 32) = make_uint4(lw[0], lw[1], lw[2], lw[3]);
            }
        }

        // ================= stage B chunk (hi/lo) =================
        {
            const uint4* sh = (const uint4*)(wsrcH + (size_t)cb * 144);
            const uint4* sl = (const uint4*)(wsrcL + (size_t)cb * 144);
            #pragma unroll
            for (int i = 0; i < 9; i++) {
                *(uint4*)(bStH + i * 16) = sh[i];
                *(uint4*)(bStL + i * 16) = sl[i];
            }
        }

        __syncthreads();

        // ================= 9 x k16 mma steps, bf16x3 split =================
        #pragma unroll 3
        for (int kt = 0; kt < 9; kt++) {
            uint32_t ah[2][4], al[2][4];
            #pragma unroll
            for (int mt = 0; mt < 2; mt++) {
                ldsm4(ah[mt], sb + OFF_AH + aoff + mt * (16 * AROWB) + kt * 32);
                ldsm4(al[mt], sb + OFF_AL + aoff + mt * (16 * AROWB) + kt * 32);
            }
            #pragma unroll
            for (int g = 0; g < 4; g++) {
                uint32_t bh[4], bl[4];
                ldsm4(bh, sb + OFF_BH + boff + g * (16 * AROWB) + kt * 32);
                ldsm4(bl, sb + OFF_BL + boff + g * (16 * AROWB) + kt * 32);
                // ntile0 frag = (r0, r2); ntile1 frag = (r1, r3)
                #pragma unroll
                for (int mt = 0; mt < 2; mt++) {
                    mma_bf16(acc[mt][g * 2 + 0], ah[mt], bh[0], bh[2]);
                    mma_bf16(acc[mt][g * 2 + 0], ah[mt], bl[0], bl[2]);
                    mma_bf16(acc[mt][g * 2 + 0], al[mt], bh[0], bh[2]);
                    mma_bf16(acc[mt][g * 2 + 1], ah[mt], bh[1], bh[3]);
                    mma_bf16(acc[mt][g * 2 + 1], ah[mt], bl[1], bl[3]);
                    mma_bf16(acc[mt][g * 2 + 1], al[mt], bh[1], bh[3]);
                }
            }
        }

        __syncthreads();
    }

    // ================= epilogue =================
    {
        const int g   = lane >> 2;
        const int tig = lane & 3;
        #pragma unroll
        for (int mt = 0; mt < 2; mt++) {
            const int mb = m0 + wm * 32 + mt * 16;
            #pragma unroll
            for (int j = 0; j < 8; j++) {
                const int f = f0 + wn * 64 + j * 8 + tig * 2;
                float2 lo = make_float2(acc[mt][j][0], acc[mt][j][1]);
                float2 hi = make_float2(acc[mt][j][2], acc[mt][j][3]);
                *(float2*)(out + (size_t)(mb + g)     * F_ + f) = lo;
                *(float2*)(out + (size_t)(mb + g + 8) * F_ + f) = hi;
            }
        }
    }
}

// ---------------- launch ---------------------------------------------------
extern "C" void kernel_launch(void* const* d_in, const int* in_sizes, int n_in,
                              void* d_out, int out_size) {
    const float* x   = (const float*)d_in[0];   // [8192,256]
    const float* cen = (const float*)d_in[1];   // [512,256]
    const float* w   = (const float*)d_in[2];   // [512,9,256]
    float* out = (float*)d_out;                 // [8192,256]

    cudaFuncSetAttribute(k_out_mma, cudaFuncAttributeMaxDynamicSharedMemorySize,
                         SMEM_TOTAL);

    k_init<<<1, 1>>>();
    int sq_warps = B_ + C_;
    k_sq<<<(sq_warps + 7) / 8, 256>>>(x, cen);
    k_dist<<<dim3(C_ / BN, B_ / BM), 256>>>(x, cen);
    k_prep<<<32, 256>>>(w);
    k_out_mma<<<dim3(F_ / 128, B_ / 128), 256, SMEM_TOTAL>>>(out);
}

// round 4
// speedup vs baseline: 2.8577x; 1.4084x over previous
#include <cuda_runtime.h>
#include <cuda_bf16.h>
#include <cstdint>

// Problem constants (fixed by reference)
#define B_   8192   // batch
#define D_   256    // input dim
#define C_   512    // num centers
#define NORD 9      // order+1
#define F_   256    // output dim
#define KTOT (C_ * NORD)   // 4608

// ---------------- scratch (static device globals; no allocation) ----------
__device__ __align__(16) float g_dist[(size_t)B_ * C_];   // 16 MB
__device__ float g_x2[B_];
__device__ float g_c2[C_];
__device__ unsigned int g_minmax[2];
// W packed in mma-fragment order:
//   record(fb,cb,kt,n16,lane) = 32 bytes: uint4 hi frag, uint4 lo frag
//   hi = {n0_b01, n0_b23, n1_b01, n1_b23}, n0: f=fb*128+n16*16+lane/4, n1: f+8
//   k within tile: b01 -> 2c0,2c0+1 ; b23 -> 2c0+8,2c0+9  (c0 = lane%4)
__device__ __align__(16) uint4 g_wf[2 * 32 * 9 * 8 * 32 * 2];   // 4.7 MB

// ==================== small helpers ========================================
__device__ __forceinline__ void mma_bf16(float* d, const uint32_t* a,
                                         uint32_t b0, uint32_t b1) {
    asm volatile(
        "mma.sync.aligned.m16n8k16.row.col.f32.bf16.bf16.f32 "
        "{%0,%1,%2,%3}, {%4,%5,%6,%7}, {%8,%9}, {%0,%1,%2,%3};"
        : "+f"(d[0]), "+f"(d[1]), "+f"(d[2]), "+f"(d[3])
        : "r"(a[0]), "r"(a[1]), "r"(a[2]), "r"(a[3]), "r"(b0), "r"(b1));
}

__device__ __forceinline__ uint32_t pack_hi(float v0, float v1) {
    __nv_bfloat162 h = __floats2bfloat162_rn(v0, v1);
    return *(uint32_t*)&h;
}
__device__ __forceinline__ uint32_t pack_lo(float v0, float v1, uint32_t hbits) {
    __nv_bfloat162 h = *(__nv_bfloat162*)&hbits;
    __nv_bfloat162 l = __floats2bfloat162_rn(v0 - __bfloat162float(h.x),
                                             v1 - __bfloat162float(h.y));
    return *(uint32_t*)&l;
}

// ---------------- kernel 0: reset min/max ---------------------------------
__global__ void k_init() {
    g_minmax[0] = 0x7f800000u;
    g_minmax[1] = 0u;
}

// ---------------- kernel 1: row squared norms ------------------------------
__global__ void __launch_bounds__(256) k_sq(const float* __restrict__ x,
                                            const float* __restrict__ cen) {
    int warp = (blockIdx.x * blockDim.x + threadIdx.x) >> 5;
    int lane = threadIdx.x & 31;
    if (warp >= B_ + C_) return;
    const float* src;
    float* dst;
    if (warp < B_) { src = x   + (size_t)warp * D_;        dst = &g_x2[warp]; }
    else           { src = cen + (size_t)(warp - B_) * D_; dst = &g_c2[warp - B_]; }
    float s = 0.f;
    const float4* p = (const float4*)src;
    #pragma unroll
    for (int i = lane; i < D_ / 4; i += 32) {
        float4 v = p[i];
        s += v.x * v.x + v.y * v.y + v.z * v.z + v.w * v.w;
    }
    #pragma unroll
    for (int o = 16; o > 0; o >>= 1) s += __shfl_xor_sync(0xffffffffu, s, o);
    if (lane == 0) *dst = s;
}

// ---------------- kernel 2: distance GEMM + global min/max ----------------
#define BM 64
#define BN 64
#define BK 16

__global__ void __launch_bounds__(256) k_dist(const float* __restrict__ x,
                                              const float* __restrict__ cen) {
    __shared__ __align__(16) float As[BK][BM + 4];
    __shared__ __align__(16) float Bs[BK][BN + 4];
    __shared__ unsigned int s_min, s_max;

    int tid = threadIdx.x;
    int m0 = blockIdx.y * BM;
    int n0 = blockIdx.x * BN;
    int tm = tid >> 4;
    int tn = tid & 15;
    int lr = tid >> 2;
    int lk = (tid & 3) * 4;

    if (tid == 0) { s_min = 0x7f800000u; s_max = 0u; }

    float acc[4][4] = {};

    for (int k0 = 0; k0 < D_; k0 += BK) {
        float4 av = *(const float4*)(x   + (size_t)(m0 + lr) * D_ + k0 + lk);
        float4 bv = *(const float4*)(cen + (size_t)(n0 + lr) * D_ + k0 + lk);
        As[lk + 0][lr] = av.x; As[lk + 1][lr] = av.y;
        As[lk + 2][lr] = av.z; As[lk + 3][lr] = av.w;
        Bs[lk + 0][lr] = bv.x; Bs[lk + 1][lr] = bv.y;
        Bs[lk + 2][lr] = bv.z; Bs[lk + 3][lr] = bv.w;
        __syncthreads();
        #pragma unroll
        for (int k = 0; k < BK; k++) {
            float4 a4 = *(const float4*)&As[k][tm * 4];
            float4 b4 = *(const float4*)&Bs[k][tn * 4];
            float a[4] = {a4.x, a4.y, a4.z, a4.w};
            float b[4] = {b4.x, b4.y, b4.z, b4.w};
            #pragma unroll
            for (int i = 0; i < 4; i++)
                #pragma unroll
                for (int j = 0; j < 4; j++)
                    acc[i][j] = fmaf(a[i], b[j], acc[i][j]);
        }
        __syncthreads();
    }

    float xs[4], cs[4];
    #pragma unroll
    for (int i = 0; i < 4; i++) xs[i] = g_x2[m0 + tm * 4 + i];
    #pragma unroll
    for (int j = 0; j < 4; j++) cs[j] = g_c2[n0 + tn * 4 + j];

    float lmin = 3.4e38f, lmax = 0.f;
    #pragma unroll
    for (int i = 0; i < 4; i++) {
        float4 st;
        float d[4];
        #pragma unroll
        for (int j = 0; j < 4; j++) {
            float d2 = xs[i] + cs[j] - 2.0f * acc[i][j];
            d[j] = sqrtf(fmaxf(d2, 0.0f));
            lmin = fminf(lmin, d[j]);
            lmax = fmaxf(lmax, d[j]);
        }
        st.x = d[0]; st.y = d[1]; st.z = d[2]; st.w = d[3];
        *(float4*)&g_dist[(size_t)(m0 + tm * 4 + i) * C_ + n0 + tn * 4] = st;
    }

    #pragma unroll
    for (int o = 16; o > 0; o >>= 1) {
        lmin = fminf(lmin, __shfl_xor_sync(0xffffffffu, lmin, o));
        lmax = fmaxf(lmax, __shfl_xor_sync(0xffffffffu, lmax, o));
    }
    if ((tid & 31) == 0) {
        atomicMin(&s_min, __float_as_uint(lmin));
        atomicMax(&s_max, __float_as_uint(lmax));
    }
    __syncthreads();
    if (tid == 0) {
        atomicMin(&g_minmax[0], s_min);
        atomicMax(&g_minmax[1], s_max);
    }
}

// ---------------- kernel 3: pack W into fragment-order hi/lo ---------------
__global__ void __launch_bounds__(256) k_prep(const float* __restrict__ w) {
    const int cb   = blockIdx.x;          // 0..31
    const int fb   = blockIdx.y;          // 0..1
    const int lane = threadIdx.x & 31;
    const int n16  = threadIdx.x >> 5;    // 0..7
    const int c0   = lane & 3;
    const int fr   = lane >> 2;
    const int f0   = fb * 128 + n16 * 16 + fr;
    const int ci0  = cb * 16 + 2 * c0;

    #pragma unroll
    for (int kt = 0; kt < NORD; kt++) {
        float v[2][4];
        #pragma unroll
        for (int e = 0; e < 2; e++) {
            v[e][0] = w[((size_t)(ci0 + 0) * NORD + kt) * F_ + f0 + e * 8];
            v[e][1] = w[((size_t)(ci0 + 1) * NORD + kt) * F_ + f0 + e * 8];
            v[e][2] = w[((size_t)(ci0 + 8) * NORD + kt) * F_ + f0 + e * 8];
            v[e][3] = w[((size_t)(ci0 + 9) * NORD + kt) * F_ + f0 + e * 8];
        }
        uint32_t hi[4], lo[4];
        #pragma unroll
        for (int e = 0; e < 2; e++) {
            hi[e * 2 + 0] = pack_hi(v[e][0], v[e][1]);
            hi[e * 2 + 1] = pack_hi(v[e][2], v[e][3]);
            lo[e * 2 + 0] = pack_lo(v[e][0], v[e][1], hi[e * 2 + 0]);
            lo[e * 2 + 1] = pack_lo(v[e][2], v[e][3], hi[e * 2 + 1]);
        }
        uint4* dst = g_wf + ((((size_t)(fb * 32 + cb) * NORD + kt) * 8 + n16) * 32
                             + lane) * 2;
        dst[0] = make_uint4(hi[0], hi[1], hi[2], hi[3]);
        dst[1] = make_uint4(lo[0], lo[1], lo[2], lo[3]);
    }
}

// ---------------- kernel 4: register-resident bf16x3 fragment GEMM ---------
// out[m,f] = sum over 32 chunks (16 centers x 9 orders). No smem, no syncs.
// CTA 128x128, 8 warps (wm 0..3, wn 0..1), warp tile 32x64.
#define IDX(mt, r, c) (((mt) * 2 + (r)) * 4 + (c))

__global__ void __launch_bounds__(256, 1) k_out_frag(float* __restrict__ out) {
    const int tid  = threadIdx.x;
    const int wid  = tid >> 5;
    const int lane = tid & 31;
    const int wm   = wid & 3;
    const int wn   = wid >> 2;
    const int m0   = blockIdx.y * 128;
    const int f0   = blockIdx.x * 128;
    const int fb   = blockIdx.x;
    const int c0   = lane & 3;
    const int lr   = lane >> 2;

    const float dmin  = __uint_as_float(g_minmax[0]);
    const float dmax  = __uint_as_float(g_minmax[1]);
    const float scale = 2.0f / (dmax - dmin);
    const float tc    = fmaf(-dmin, scale, -1.0f);   // t = d*scale + tc

    // distance row pointers for this thread's 4 rows (q = mt*2 + r)
    const float* dp[4];
    #pragma unroll
    for (int q = 0; q < 4; q++) {
        int row = m0 + wm * 32 + (q >> 1) * 16 + (q & 1) * 8 + lr;
        dp[q] = g_dist + (size_t)row * C_ + 2 * c0;
    }

    // W fragment base for this (fb, wn, lane): byte offset for (cb,kt,g):
    //   base + cb*73728 + (kt*8 + g)*1024
    const char* wfb = (const char*)g_wf
        + ((size_t)(fb * 32) * NORD * 8 + wn * 4) * 1024 + lane * 32;

    float acc[2][8][4];
    #pragma unroll
    for (int mt = 0; mt < 2; mt++)
        #pragma unroll
        for (int j = 0; j < 8; j++)
            #pragma unroll
            for (int e = 0; e < 4; e++) acc[mt][j][e] = 0.0f;

    // prefetched distances for current chunk
    float2 dv[8];
    #pragma unroll
    for (int q = 0; q < 4; q++) {
        dv[q * 2 + 0] = *(const float2*)(dp[q]);
        dv[q * 2 + 1] = *(const float2*)(dp[q] + 8);
    }

    for (int cb = 0; cb < 32; cb++) {
        // ---- t for this chunk ----
        float t[16], pa[16], pb[16];
        #pragma unroll
        for (int q = 0; q < 4; q++) {
            t[q * 4 + 0] = fmaf(dv[q * 2 + 0].x, scale, tc);
            t[q * 4 + 1] = fmaf(dv[q * 2 + 0].y, scale, tc);
            t[q * 4 + 2] = fmaf(dv[q * 2 + 1].x, scale, tc);
            t[q * 4 + 3] = fmaf(dv[q * 2 + 1].y, scale, tc);
        }
        // ---- prefetch next chunk's distances ----
        if (cb < 31) {
            #pragma unroll
            for (int q = 0; q < 4; q++) {
                dv[q * 2 + 0] = *(const float2*)(dp[q] + (cb + 1) * 16);
                dv[q * 2 + 1] = *(const float2*)(dp[q] + (cb + 1) * 16 + 8);
            }
        }
        #pragma unroll
        for (int i = 0; i < 16; i++) { pa[i] = 1.0f; pb[i] = t[i]; }

        const char* wpc = wfb + (size_t)cb * (NORD * 8 * 1024);
        uint4 bh = *(const uint4*)(wpc);
        uint4 bl = *(const uint4*)(wpc + 16);
        uint32_t off = 0;

        #pragma unroll
        for (int kt = 0; kt < NORD; kt++) {
            // ---- A fragments for order kt ----
            uint32_t ah[2][4], al[2][4];
            if (kt == 0) {
                #pragma unroll
                for (int mt = 0; mt < 2; mt++)
                    #pragma unroll
                    for (int e = 0; e < 4; e++) {
                        ah[mt][e] = 0x3F803F80u;  // bf16 1.0 pair
                        al[mt][e] = 0u;
                    }
            } else {
                if (kt >= 2) {
                    const float an = (2.0f * kt - 1.0f) / (float)kt;
                    const float bn = (float)(kt - 1) / (float)kt;
                    #pragma unroll
                    for (int i = 0; i < 16; i++) {
                        float p2 = an * t[i] * pb[i] - bn * pa[i];
                        pa[i] = pb[i];
                        pb[i] = p2;
                    }
                }
                #pragma unroll
                for (int mt = 0; mt < 2; mt++) {
                    ah[mt][0] = pack_hi(pb[IDX(mt,0,0)], pb[IDX(mt,0,1)]);
                    ah[mt][1] = pack_hi(pb[IDX(mt,1,0)], pb[IDX(mt,1,1)]);
                    ah[mt][2] = pack_hi(pb[IDX(mt,0,2)], pb[IDX(mt,0,3)]);
                    ah[mt][3] = pack_hi(pb[IDX(mt,1,2)], pb[IDX(mt,1,3)]);
                    al[mt][0] = pack_lo(pb[IDX(mt,0,0)], pb[IDX(mt,0,1)], ah[mt][0]);
                    al[mt][1] = pack_lo(pb[IDX(mt,1,0)], pb[IDX(mt,1,1)], ah[mt][1]);
                    al[mt][2] = pack_lo(pb[IDX(mt,0,2)], pb[IDX(mt,0,3)], ah[mt][2]);
                    al[mt][3] = pack_lo(pb[IDX(mt,1,2)], pb[IDX(mt,1,3)], ah[mt][3]);
                }
            }

            // ---- 4 n16-groups, B via prefetched LDG.128 ----
            #pragma unroll
            for (int g = 0; g < 4; g++) {
                uint32_t noff = off + ((g == 3) ? 5120u : 1024u);
                uint4 bhn, bln;
                if (!(kt == NORD - 1 && g == 3)) {
                    bhn = *(const uint4*)(wpc + noff);
                    bln = *(const uint4*)(wpc + noff + 16);
                }
                #pragma unroll
                for (int mt = 0; mt < 2; mt++) {
                    mma_bf16(acc[mt][g * 2 + 0], ah[mt], bh.x, bh.y);
                    mma_bf16(acc[mt][g * 2 + 1], ah[mt], bh.z, bh.w);
                    mma_bf16(acc[mt][g * 2 + 0], ah[mt], bl.x, bl.y);
                    mma_bf16(acc[mt][g * 2 + 1], ah[mt], bl.z, bl.w);
                    mma_bf16(acc[mt][g * 2 + 0], al[mt], bh.x, bh.y);
                    mma_bf16(acc[mt][g * 2 + 1], al[mt], bh.z, bh.w);
                }
                bh = bhn; bl = bln; off = noff;
            }
        }
    }

    // ---- epilogue (same fragment->gmem mapping as validated round 3) ----
    {
        const int g   = lane >> 2;
        const int tig = lane & 3;
        #pragma unroll
        for (int mt = 0; mt < 2; mt++) {
            const int mb = m0 + wm * 32 + mt * 16;
            #pragma unroll
            for (int j = 0; j < 8; j++) {
                const int f = f0 + wn * 64 + j * 8 + tig * 2;
                float2 lo = make_float2(acc[mt][j][0], acc[mt][j][1]);
                float2 hi = make_float2(acc[mt][j][2], acc[mt][j][3]);
                *(float2*)(out + (size_t)(mb + g)     * F_ + f) = lo;
                *(float2*)(out + (size_t)(mb + g + 8) * F_ + f) = hi;
            }
        }
    }
}

// ---------------- launch ---------------------------------------------------
extern "C" void kernel_launch(void* const* d_in, const int* in_sizes, int n_in,
                              void* d_out, int out_size) {
    const float* x   = (const float*)d_in[0];   // [8192,256]
    const float* cen = (const float*)d_in[1];   // [512,256]
    const float* w   = (const float*)d_in[2];   // [512,9,256]
    float* out = (float*)d_out;                 // [8192,256]

    k_init<<<1, 1>>>();
    int sq_warps = B_ + C_;
    k_sq<<<(sq_warps + 7) / 8, 256>>>(x, cen);
    k_dist<<<dim3(C_ / BN, B_ / BM), 256>>>(x, cen);
    k_prep<<<dim3(32, 2), 256>>>(w);
    k_out_frag<<<dim3(F_ / 128, B_ / 128), 256>>>(out);
}

// round 5
// speedup vs baseline: 3.2843x; 1.1493x over previous
#include <cuda_runtime.h>
#include <cuda_bf16.h>
#include <cstdint>

// Problem constants (fixed by reference)
#define B_   8192   // batch
#define D_   256    // input dim
#define C_   512    // num centers
#define NORD 9      // order+1
#define F_   256    // output dim
#define KTOT (C_ * NORD)   // 4608

// ---------------- scratch (static device globals; no allocation) ----------
__device__ __align__(16) float g_dist[(size_t)B_ * C_];   // 16 MB
__device__ float g_x2[B_];
__device__ float g_c2[C_];
__device__ float g_bias[F_];
__device__ unsigned int g_minmax[2];
// W packed in mma-fragment order (record = 32B: uint4 hi, uint4 lo)
__device__ __align__(16) uint4 g_wf[2 * 32 * NORD * 8 * 32 * 2];   // 4.7 MB
// x packed in A-fragment order: [mi(512)][kt(16)][lane(32)] -> {hi,lo}
__device__ __align__(16) uint4 g_xf[(B_ / 16) * 16 * 32 * 2];      // 8 MB
// centers packed in B-fragment order: [ni(32)][kt(16)][lane(32)] -> {hi,lo}
__device__ __align__(16) uint4 g_cf[(C_ / 16) * 16 * 32 * 2];      // 512 KB

// ==================== small helpers ========================================
__device__ __forceinline__ void mma_bf16(float* d, const uint32_t* a,
                                         uint32_t b0, uint32_t b1) {
    asm volatile(
        "mma.sync.aligned.m16n8k16.row.col.f32.bf16.bf16.f32 "
        "{%0,%1,%2,%3}, {%4,%5,%6,%7}, {%8,%9}, {%0,%1,%2,%3};"
        : "+f"(d[0]), "+f"(d[1]), "+f"(d[2]), "+f"(d[3])
        : "r"(a[0]), "r"(a[1]), "r"(a[2]), "r"(a[3]), "r"(b0), "r"(b1));
}

__device__ __forceinline__ uint32_t pack_hi(float v0, float v1) {
    __nv_bfloat162 h = __floats2bfloat162_rn(v0, v1);
    return *(uint32_t*)&h;
}
__device__ __forceinline__ uint32_t pack_lo(float v0, float v1, uint32_t hbits) {
    __nv_bfloat162 h = *(__nv_bfloat162*)&hbits;
    __nv_bfloat162 l = __floats2bfloat162_rn(v0 - __bfloat162float(h.x),
                                             v1 - __bfloat162float(h.y));
    return *(uint32_t*)&l;
}

// ---------------- kernel 1: row squared norms + global inits ---------------
__global__ void __launch_bounds__(256) k_sq(const float* __restrict__ x,
                                            const float* __restrict__ cen) {
    if (blockIdx.x == 0) {
        if (threadIdx.x == 0) { g_minmax[0] = 0x7f800000u; g_minmax[1] = 0u; }
        g_bias[threadIdx.x] = 0.0f;
    }
    int warp = (blockIdx.x * blockDim.x + threadIdx.x) >> 5;
    int lane = threadIdx.x & 31;
    if (warp >= B_ + C_) return;
    const float* src;
    float* dst;
    if (warp < B_) { src = x   + (size_t)warp * D_;        dst = &g_x2[warp]; }
    else           { src = cen + (size_t)(warp - B_) * D_; dst = &g_c2[warp - B_]; }
    float s = 0.f;
    const float4* p = (const float4*)src;
    #pragma unroll
    for (int i = lane; i < D_ / 4; i += 32) {
        float4 v = p[i];
        s += v.x * v.x + v.y * v.y + v.z * v.z + v.w * v.w;
    }
    #pragma unroll
    for (int o = 16; o > 0; o >>= 1) s += __shfl_xor_sync(0xffffffffu, s, o);
    if (lane == 0) *dst = s;
}

// ---------------- kernel 2a: split x into A-fragment order -----------------
// record(mi,kt,lane): hi = {(r,k01),(r+8,k01),(r,k89),(r+8,k89)}
__global__ void __launch_bounds__(256) k_prepx(const float* __restrict__ x) {
    int gid  = blockIdx.x * 256 + threadIdx.x;     // (mi*16+kt)*32+lane
    int lane = gid & 31;
    int kt   = (gid >> 5) & 15;
    int mi   = gid >> 9;
    int c0 = lane & 3, lr = lane >> 2;
    const float* px = x + (size_t)(mi * 16 + lr) * D_ + kt * 16 + 2 * c0;
    float2 v0 = *(const float2*)(px);
    float2 v1 = *(const float2*)(px + 8 * D_);
    float2 v2 = *(const float2*)(px + 8);
    float2 v3 = *(const float2*)(px + 8 * D_ + 8);
    uint32_t h0 = pack_hi(v0.x, v0.y), h1 = pack_hi(v1.x, v1.y);
    uint32_t h2 = pack_hi(v2.x, v2.y), h3 = pack_hi(v3.x, v3.y);
    uint4* dst = g_xf + (size_t)gid * 2;
    dst[0] = make_uint4(h0, h1, h2, h3);
    dst[1] = make_uint4(pack_lo(v0.x, v0.y, h0), pack_lo(v1.x, v1.y, h1),
                        pack_lo(v2.x, v2.y, h2), pack_lo(v3.x, v3.y, h3));
}

// ---------------- kernel 2b: split centers into B-fragment order -----------
// record(ni,kt,lane): hi = {n0_k01, n0_k89, n1_k01, n1_k89}, n0=ni*16+lr, n1=n0+8
__global__ void __launch_bounds__(256) k_prepc(const float* __restrict__ cen) {
    int gid  = blockIdx.x * 256 + threadIdx.x;     // (ni*16+kt)*32+lane
    int lane = gid & 31;
    int kt   = (gid >> 5) & 15;
    int ni   = gid >> 9;
    int c0 = lane & 3, lr = lane >> 2;
    const float* pc = cen + (size_t)(ni * 16 + lr) * D_ + kt * 16 + 2 * c0;
    float2 v0 = *(const float2*)(pc);
    float2 v1 = *(const float2*)(pc + 8);
    float2 v2 = *(const float2*)(pc + 8 * D_);
    float2 v3 = *(const float2*)(pc + 8 * D_ + 8);
    uint32_t h0 = pack_hi(v0.x, v0.y), h1 = pack_hi(v1.x, v1.y);
    uint32_t h2 = pack_hi(v2.x, v2.y), h3 = pack_hi(v3.x, v3.y);
    uint4* dst = g_cf + (size_t)gid * 2;
    dst[0] = make_uint4(h0, h1, h2, h3);
    dst[1] = make_uint4(pack_lo(v0.x, v0.y, h0), pack_lo(v1.x, v1.y, h1),
                        pack_lo(v2.x, v2.y, h2), pack_lo(v3.x, v3.y, h3));
}

// ---------------- kernel 3: pack W (fragment order) + exact fp32 bias ------
__global__ void __launch_bounds__(256) k_prep(const float* __restrict__ w) {
    const int cb   = blockIdx.x;          // 0..31
    const int fb   = blockIdx.y;          // 0..1
    const int lane = threadIdx.x & 31;
    const int n16  = threadIdx.x >> 5;    // 0..7
    const int c0   = lane & 3;
    const int fr   = lane >> 2;
    const int f0   = fb * 128 + n16 * 16 + fr;
    const int ci0  = cb * 16 + 2 * c0;

    #pragma unroll
    for (int kt = 0; kt < NORD; kt++) {
        float v[2][4];
        #pragma unroll
        for (int e = 0; e < 2; e++) {
            v[e][0] = w[((size_t)(ci0 + 0) * NORD + kt) * F_ + f0 + e * 8];
            v[e][1] = w[((size_t)(ci0 + 1) * NORD + kt) * F_ + f0 + e * 8];
            v[e][2] = w[((size_t)(ci0 + 8) * NORD + kt) * F_ + f0 + e * 8];
            v[e][3] = w[((size_t)(ci0 + 9) * NORD + kt) * F_ + f0 + e * 8];
        }
        if (kt == 0) {
            atomicAdd(&g_bias[f0],     v[0][0] + v[0][1] + v[0][2] + v[0][3]);
            atomicAdd(&g_bias[f0 + 8], v[1][0] + v[1][1] + v[1][2] + v[1][3]);
        }
        uint32_t hi[4], lo[4];
        #pragma unroll
        for (int e = 0; e < 2; e++) {
            hi[e * 2 + 0] = pack_hi(v[e][0], v[e][1]);
            hi[e * 2 + 1] = pack_hi(v[e][2], v[e][3]);
            lo[e * 2 + 0] = pack_lo(v[e][0], v[e][1], hi[e * 2 + 0]);
            lo[e * 2 + 1] = pack_lo(v[e][2], v[e][3], hi[e * 2 + 1]);
        }
        uint4* dst = g_wf + ((((size_t)(fb * 32 + cb) * NORD + kt) * 8 + n16) * 32
                             + lane) * 2;
        dst[0] = make_uint4(hi[0], hi[1], hi[2], hi[3]);
        dst[1] = make_uint4(lo[0], lo[1], lo[2], lo[3]);
    }
}

// ---------------- kernel 4: tensorized distance GEMM + min/max ------------
// dot[m,n] via bf16x3 fragments; d = sqrt(max(x2+c2-2dot,0)); global min/max.
__global__ void __launch_bounds__(256) k_dist_mma() {
    __shared__ unsigned int s_min, s_max;
    const int tid  = threadIdx.x;
    const int wid  = tid >> 5;
    const int lane = tid & 31;
    const int wm   = wid & 3;
    const int wn   = wid >> 2;
    const int m0   = blockIdx.y * 128;
    const int n0   = blockIdx.x * 128;
    const int tig  = lane & 3;
    const int lr   = lane >> 2;

    if (tid == 0) { s_min = 0x7f800000u; s_max = 0u; }

    float acc[2][8][4];
    #pragma unroll
    for (int mt = 0; mt < 2; mt++)
        #pragma unroll
        for (int j = 0; j < 8; j++)
            #pragma unroll
            for (int e = 0; e < 4; e++) acc[mt][j][e] = 0.0f;

    const int mi0 = (m0 >> 4) + wm * 2;
    const int ni0 = (n0 >> 4) + wn * 4;

    #pragma unroll 4
    for (int kt = 0; kt < 16; kt++) {
        uint4 ah[2], al[2];
        #pragma unroll
        for (int mt = 0; mt < 2; mt++) {
            const uint4* ap = g_xf + ((size_t)((mi0 + mt) * 16 + kt) * 32 + lane) * 2;
            ah[mt] = ap[0];
            al[mt] = ap[1];
        }
        #pragma unroll
        for (int g = 0; g < 4; g++) {
            const uint4* bp = g_cf + ((size_t)((ni0 + g) * 16 + kt) * 32 + lane) * 2;
            uint4 bh = bp[0], bl = bp[1];
            #pragma unroll
            for (int mt = 0; mt < 2; mt++) {
                mma_bf16(acc[mt][g * 2 + 0], (const uint32_t*)&ah[mt], bh.x, bh.y);
                mma_bf16(acc[mt][g * 2 + 1], (const uint32_t*)&ah[mt], bh.z, bh.w);
                mma_bf16(acc[mt][g * 2 + 0], (const uint32_t*)&ah[mt], bl.x, bl.y);
                mma_bf16(acc[mt][g * 2 + 1], (const uint32_t*)&ah[mt], bl.z, bl.w);
                mma_bf16(acc[mt][g * 2 + 0], (const uint32_t*)&al[mt], bh.x, bh.y);
                mma_bf16(acc[mt][g * 2 + 1], (const uint32_t*)&al[mt], bh.z, bh.w);
            }
        }
    }

    // epilogue: distances + min/max
    float x2r[2][2];
    #pragma unroll
    for (int mt = 0; mt < 2; mt++)
        #pragma unroll
        for (int rh = 0; rh < 2; rh++)
            x2r[mt][rh] = g_x2[m0 + wm * 32 + mt * 16 + rh * 8 + lr];

    float lmin = 3.4e38f, lmax = 0.f;
    #pragma unroll
    for (int mt = 0; mt < 2; mt++) {
        #pragma unroll
        for (int j = 0; j < 8; j++) {
            const int n = n0 + wn * 64 + j * 8 + tig * 2;
            float2 c2v = *(const float2*)&g_c2[n];
            #pragma unroll
            for (int rh = 0; rh < 2; rh++) {
                float xx = x2r[mt][rh];
                float d0 = sqrtf(fmaxf(xx + c2v.x - 2.0f * acc[mt][j][rh * 2 + 0], 0.f));
                float d1 = sqrtf(fmaxf(xx + c2v.y - 2.0f * acc[mt][j][rh * 2 + 1], 0.f));
                lmin = fminf(lmin, fminf(d0, d1));
                lmax = fmaxf(lmax, fmaxf(d0, d1));
                const int row = m0 + wm * 32 + mt * 16 + rh * 8 + lr;
                *(float2*)&g_dist[(size_t)row * C_ + n] = make_float2(d0, d1);
            }
        }
    }

    #pragma unroll
    for (int o = 16; o > 0; o >>= 1) {
        lmin = fminf(lmin, __shfl_xor_sync(0xffffffffu, lmin, o));
        lmax = fmaxf(lmax, __shfl_xor_sync(0xffffffffu, lmax, o));
    }
    __syncthreads();   // s_min/s_max init visible
    if (lane == 0) {
        atomicMin(&s_min, __float_as_uint(lmin));
        atomicMax(&s_max, __float_as_uint(lmax));
    }
    __syncthreads();
    if (tid == 0) {
        atomicMin(&g_minmax[0], s_min);
        atomicMax(&g_minmax[1], s_max);
    }
}

// ---------------- kernel 5: register-resident bf16x3 fragment GEMM ---------
// kt=0 (P0==1) folded into exact fp32 bias; GEMM runs orders 1..8 only.
#define IDX(mt, r, c) (((mt) * 2 + (r)) * 4 + (c))

__global__ void __launch_bounds__(256, 1) k_out_frag(float* __restrict__ out) {
    const int tid  = threadIdx.x;
    const int wid  = tid >> 5;
    const int lane = tid & 31;
    const int wm   = wid & 3;
    const int wn   = wid >> 2;
    const int m0   = blockIdx.y * 128;
    const int f0   = blockIdx.x * 128;
    const int fb   = blockIdx.x;
    const int c0   = lane & 3;
    const int lr   = lane >> 2;

    const float dmin  = __uint_as_float(g_minmax[0]);
    const float dmax  = __uint_as_float(g_minmax[1]);
    const float scale = 2.0f / (dmax - dmin);
    const float tc    = fmaf(-dmin, scale, -1.0f);

    const float* dp[4];
    #pragma unroll
    for (int q = 0; q < 4; q++) {
        int row = m0 + wm * 32 + (q >> 1) * 16 + (q & 1) * 8 + lr;
        dp[q] = g_dist + (size_t)row * C_ + 2 * c0;
    }

    const char* wfb = (const char*)g_wf
        + ((size_t)(fb * 32) * NORD * 8 + wn * 4) * 1024 + lane * 32;

    // init accumulators with the exact P0 bias
    float acc[2][8][4];
    #pragma unroll
    for (int j = 0; j < 8; j++) {
        float2 bz = *(const float2*)&g_bias[f0 + wn * 64 + j * 8 + (lane & 3) * 2];
        #pragma unroll
        for (int mt = 0; mt < 2; mt++) {
            acc[mt][j][0] = bz.x; acc[mt][j][1] = bz.y;
            acc[mt][j][2] = bz.x; acc[mt][j][3] = bz.y;
        }
    }

    float2 dv[8];
    #pragma unroll
    for (int q = 0; q < 4; q++) {
        dv[q * 2 + 0] = *(const float2*)(dp[q]);
        dv[q * 2 + 1] = *(const float2*)(dp[q] + 8);
    }

    for (int cb = 0; cb < 32; cb++) {
        float t[16], pa[16], pb[16];
        #pragma unroll
        for (int q = 0; q < 4; q++) {
            t[q * 4 + 0] = fmaf(dv[q * 2 + 0].x, scale, tc);
            t[q * 4 + 1] = fmaf(dv[q * 2 + 0].y, scale, tc);
            t[q * 4 + 2] = fmaf(dv[q * 2 + 1].x, scale, tc);
            t[q * 4 + 3] = fmaf(dv[q * 2 + 1].y, scale, tc);
        }
        if (cb < 31) {
            #pragma unroll
            for (int q = 0; q < 4; q++) {
                dv[q * 2 + 0] = *(const float2*)(dp[q] + (cb + 1) * 16);
                dv[q * 2 + 1] = *(const float2*)(dp[q] + (cb + 1) * 16 + 8);
            }
        }
        #pragma unroll
        for (int i = 0; i < 16; i++) { pa[i] = 1.0f; pb[i] = t[i]; }

        const char* wpc = wfb + (size_t)cb * (NORD * 8 * 1024);
        uint4 bh = *(const uint4*)(wpc + 8192);        // (kt=1, g=0)
        uint4 bl = *(const uint4*)(wpc + 8192 + 16);
        uint32_t off = 8192;

        #pragma unroll
        for (int kt = 1; kt < NORD; kt++) {
            uint32_t ah[2][4], al[2][4];
            if (kt >= 2) {
                const float an = (2.0f * kt - 1.0f) / (float)kt;
                const float bn = (float)(kt - 1) / (float)kt;
                #pragma unroll
                for (int i = 0; i < 16; i++) {
                    float p2 = an * t[i] * pb[i] - bn * pa[i];
                    pa[i] = pb[i];
                    pb[i] = p2;
                }
            }
            #pragma unroll
            for (int mt = 0; mt < 2; mt++) {
                ah[mt][0] = pack_hi(pb[IDX(mt,0,0)], pb[IDX(mt,0,1)]);
                ah[mt][1] = pack_hi(pb[IDX(mt,1,0)], pb[IDX(mt,1,1)]);
                ah[mt][2] = pack_hi(pb[IDX(mt,0,2)], pb[IDX(mt,0,3)]);
                ah[mt][3] = pack_hi(pb[IDX(mt,1,2)], pb[IDX(mt,1,3)]);
                al[mt][0] = pack_lo(pb[IDX(mt,0,0)], pb[IDX(mt,0,1)], ah[mt][0]);
                al[mt][1] = pack_lo(pb[IDX(mt,1,0)], pb[IDX(mt,1,1)], ah[mt][1]);
                al[mt][2] = pack_lo(pb[IDX(mt,0,2)], pb[IDX(mt,0,3)], ah[mt][2]);
                al[mt][3] = pack_lo(pb[IDX(mt,1,2)], pb[IDX(mt,1,3)], ah[mt][3]);
            }

            #pragma unroll
            for (int g = 0; g < 4; g++) {
                uint32_t noff = off + ((g == 3) ? 5120u : 1024u);
                uint4 bhn, bln;
                if (!(kt == NORD - 1 && g == 3)) {
                    bhn = *(const uint4*)(wpc + noff);
                    bln = *(const uint4*)(wpc + noff + 16);
                }
                #pragma unroll
                for (int mt = 0; mt < 2; mt++) {
                    mma_bf16(acc[mt][g * 2 + 0], ah[mt], bh.x, bh.y);
                    mma_bf16(acc[mt][g * 2 + 1], ah[mt], bh.z, bh.w);
                    mma_bf16(acc[mt][g * 2 + 0], ah[mt], bl.x, bl.y);
                    mma_bf16(acc[mt][g * 2 + 1], ah[mt], bl.z, bl.w);
                    mma_bf16(acc[mt][g * 2 + 0], al[mt], bh.x, bh.y);
                    mma_bf16(acc[mt][g * 2 + 1], al[mt], bh.z, bh.w);
                }
                bh = bhn; bl = bln; off = noff;
            }
        }
    }

    // epilogue
    {
        const int g   = lane >> 2;
        const int tig = lane & 3;
        #pragma unroll
        for (int mt = 0; mt < 2; mt++) {
            const int mb = m0 + wm * 32 + mt * 16;
            #pragma unroll
            for (int j = 0; j < 8; j++) {
                const int f = f0 + wn * 64 + j * 8 + tig * 2;
                float2 lo = make_float2(acc[mt][j][0], acc[mt][j][1]);
                float2 hi = make_float2(acc[mt][j][2], acc[mt][j][3]);
                *(float2*)(out + (size_t)(mb + g)     * F_ + f) = lo;
                *(float2*)(out + (size_t)(mb + g + 8) * F_ + f) = hi;
            }
        }
    }
}

// ---------------- launch ---------------------------------------------------
extern "C" void kernel_launch(void* const* d_in, const int* in_sizes, int n_in,
                              void* d_out, int out_size) {
    const float* x   = (const float*)d_in[0];   // [8192,256]
    const float* cen = (const float*)d_in[1];   // [512,256]
    const float* w   = (const float*)d_in[2];   // [512,9,256]
    float* out = (float*)d_out;                 // [8192,256]

    int sq_warps = B_ + C_;
    k_sq<<<(sq_warps + 7) / 8, 256>>>(x, cen);
    k_prepx<<<(B_ / 16) * 16 * 32 / 256, 256>>>(x);       // 1024 blocks
    k_prepc<<<(C_ / 16) * 16 * 32 / 256, 256>>>(cen);     // 64 blocks
    k_prep<<<dim3(32, 2), 256>>>(w);
    k_dist_mma<<<dim3(C_ / 128, B_ / 128), 256>>>();
    k_out_frag<<<dim3(F_ / 128, B_ / 128), 256>>>(out);
}